// round 14
// baseline (speedup 1.0000x reference)
#include <cuda_runtime.h>
#include <cuda_bf16.h>
#include <cstdint>

#define BB 2
#define TT 2048
#define EE 768
#define SS 96
#define HH 150
#define HS 168
#define WW 8
#define E3 2304
#define NSPAN (BB*SS)      // 192
#define NROW (NSPAN*WW)    // 1536
#define NPAIR 9312
#define NPAIRP 9344        // 73*128
#define KPR 6912           // 3*E3 interleaved split K
#define KA 2304            // 3*768
#define K2 480             // 3*160
#define NCHA2 36
#define ABUF 26624         // 128 rows * 208 B
#define WBUF 33280         // 160 rows * 208 B
#define SMEMG (2*ABUF + 2*WBUF)        // 119808
#define A2RS 976
#define A2BYTES (64*A2RS)              // 62464
#define W2CB 12800
#define SMEMPE (A2BYTES + 2*W2CB)      // 88064

// -------- device scratch --------
__device__ int   d_starts[NSPAN];
__device__ __align__(16) float d_g[NSPAN * E3];
__device__ float d_part[3 * 12 * 256 * 160];
__device__ float d_ap[8 * NROW * 160];
__device__ float d_h1[NROW * 160];
__device__ float d_at[NROW];
__device__ float d_A[NSPAN * HH];
__device__ float d_Bt[NSPAN * HH];
__device__ float d_ms[NSPAN];
__device__ int   d_pi[NPAIRP], d_pj[NPAIRP];
__device__ __align__(16) __nv_bfloat16 d_Wi[160 * KPR];
__device__ __align__(16) __nv_bfloat16 d_AWi[160 * KA];
__device__ __align__(16) __nv_bfloat16 d_W2i[160 * K2];
__device__ float d_Cg2[2][(size_t)NPAIRP * 160];

// -------- generic-PTX helpers --------
__device__ __forceinline__ uint32_t smem_u32(const void* p) {
    uint32_t a;
    asm("{ .reg .u64 t; cvta.to.shared.u64 t, %1; cvt.u32.u64 %0, t; }"
        : "=r"(a) : "l"(p));
    return a;
}
#define CP_ASYNC16(dst, src) \
    asm volatile("cp.async.cg.shared.global [%0], [%1], 16;" \
                 :: "r"(dst), "l"(src) : "memory")
#define CP_COMMIT() asm volatile("cp.async.commit_group;" ::: "memory")
#define CP_WAIT0()  asm volatile("cp.async.wait_group 0;" ::: "memory")

__device__ __forceinline__ void mma16816(float c[4], uint32_t a0, uint32_t a1,
                                         uint32_t a2, uint32_t a3,
                                         uint32_t b0, uint32_t b1) {
    asm volatile(
        "mma.sync.aligned.m16n8k16.row.col.f32.bf16.bf16.f32 "
        "{%0,%1,%2,%3}, {%4,%5,%6,%7}, {%8,%9}, {%0,%1,%2,%3};"
        : "+f"(c[0]), "+f"(c[1]), "+f"(c[2]), "+f"(c[3])
        : "r"(a0), "r"(a1), "r"(a2), "r"(a3), "r"(b0), "r"(b1));
}

__device__ __forceinline__ void split_bf16(float p, unsigned short& hu,
                                           unsigned short& lu) {
    asm("cvt.rn.bf16.f32 %0, %1;" : "=h"(hu) : "f"(p));
    float hf = __uint_as_float(((uint32_t)hu) << 16);
    float l = p - hf;
    asm("cvt.rn.bf16.f32 %0, %1;" : "=h"(lu) : "f"(l));
}

// ---------------------------------------------------------------------------
__global__ void k_prep0(const void* sp) {
    if (blockIdx.x == 72) {
        __shared__ int is64;
        if (threadIdx.x == 0) {
            const int* w32 = (const int*)sp;
            int z = 1;
            for (int i = 1; i < 64; i += 2) if (w32[i] != 0) { z = 0; break; }
            is64 = z;
        }
        __syncthreads();
        int i = threadIdx.x;
        if (i < NSPAN) {
            if (is64) d_starts[i] = (int)((const long long*)sp)[i];
            else      d_starts[i] = ((const int*)sp)[i];
        }
        return;
    }
    int idx = blockIdx.x * 256 + threadIdx.x;
    int b = idx / (SS * SS), r = idx % (SS * SS);
    int i = r / SS, j = r % SS;
    if (j >= i) {
        int row = b * 4656 + i * SS - i * (i - 1) / 2 + (j - i);
        d_pi[row] = b * SS + i;
        d_pj[row] = b * SS + j;
    }
    if (idx < NPAIRP - NPAIR) {
        d_pi[NPAIR + idx] = NSPAN - 1;
        d_pj[NPAIR + idx] = NSPAN - 1;
    }
}

// ---------------------------------------------------------------------------
// k_wprep: interleaved bf16 splits, n-fast indexing for coalesced reads.
// ---------------------------------------------------------------------------
__global__ void k_wprep(const float* __restrict__ pw1,
                        const float* __restrict__ aw1,
                        const float* __restrict__ pw2) {
    int idx = blockIdx.x * blockDim.x + threadIdx.x;
    const int S0 = 160 * E3;
    const int S1 = 160 * 768;
    const int S2 = 160 * 160;
    if (idx >= S0 + S1 + S2) return;
    float w = 0.f;
    unsigned short* dst;
    if (idx < S0) {
        int n = idx % 160, k = idx / 160;
        if (n < HH) w = pw1[(size_t)2 * E3 * HH + (size_t)k * HH + n];
        dst = (unsigned short*)d_Wi + (size_t)n * KPR + 3 * k;
    } else if (idx < S0 + S1) {
        int i2 = idx - S0;
        int n = i2 % 160, k = i2 / 160;
        if (n < HH) w = aw1[(size_t)k * HH + n];
        dst = (unsigned short*)d_AWi + (size_t)n * KA + 3 * k;
    } else {
        int i3 = idx - S0 - S1;
        int n = i3 % 160, k = i3 / 160;
        if (n < HH && k < HH) w = pw2[(size_t)k * HH + n];
        dst = (unsigned short*)d_W2i + (size_t)n * K2 + 3 * k;
    }
    unsigned short hu, lu;
    split_bf16(w, hu, lu);
    dst[0] = hu; dst[1] = lu; dst[2] = hu;
}

// ---------------------------------------------------------------------------
__device__ __forceinline__ void cpw_generic(uint32_t wdst, const char* srcbase,
                                            size_t rstride, int choff, int tid) {
    #pragma unroll
    for (int v = 0; v < 2; v++) {
        int unit = tid + 256 * v;
        if (unit < 320) {
            int n = unit >> 1, kh = unit & 1;
            const char* src = srcbase + (size_t)n * rstride + choff + kh * 96;
            uint32_t dst = wdst + n * 208 + kh * 96;
            #pragma unroll
            for (int q = 0; q < 6; q++)
                CP_ASYNC16(dst + q * 16, src + q * 16);
        }
    }
}

__device__ __forceinline__ void pack_store(char* dst, int aoff,
                                           const float* pv) {
    unsigned short us[48];
    #pragma unroll
    for (int k = 0; k < 16; k++) {
        unsigned short hu, lu;
        split_bf16(pv[k], hu, lu);
        us[3*k+0] = hu; us[3*k+1] = hu; us[3*k+2] = lu;
    }
    uint32_t u[24];
    #pragma unroll
    for (int j = 0; j < 24; j++)
        u[j] = (uint32_t)us[2*j] | ((uint32_t)us[2*j+1] << 16);
    uint4* d = (uint4*)(dst + aoff);
    d[0] = make_uint4(u[0],  u[1],  u[2],  u[3]);
    d[1] = make_uint4(u[4],  u[5],  u[6],  u[7]);
    d[2] = make_uint4(u[8],  u[9],  u[10], u[11]);
    d[3] = make_uint4(u[12], u[13], u[14], u[15]);
    d[4] = make_uint4(u[16], u[17], u[18], u[19]);
    d[5] = make_uint4(u[20], u[21], u[22], u[23]);
}

// ---------------------------------------------------------------------------
__device__ __forceinline__ void gemm_chunk(const char* A, const char* W,
                                           int wm, int wn, int g, int tg,
                                           float c[2][10][4]) {
    #pragma unroll
    for (int s = 0; s < 6; s++) {
        uint32_t a[2][4];
        #pragma unroll
        for (int m2 = 0; m2 < 2; m2++) {
            int r0 = (wm * 32 + m2 * 16 + g) * 208 + s * 32 + tg * 4;
            a[m2][0] = *(const uint32_t*)(A + r0);
            a[m2][1] = *(const uint32_t*)(A + r0 + 8 * 208);
            a[m2][2] = *(const uint32_t*)(A + r0 + 16);
            a[m2][3] = *(const uint32_t*)(A + r0 + 8 * 208 + 16);
        }
        #pragma unroll
        for (int t = 0; t < 10; t++) {
            int wo = (wn * 80 + 8 * t + g) * 208 + s * 32 + tg * 4;
            uint32_t b0 = *(const uint32_t*)(W + wo);
            uint32_t b1 = *(const uint32_t*)(W + wo + 16);
            mma16816(c[0][t], a[0][0], a[0][1], a[0][2], a[0][3], b0, b1);
            mma16816(c[1][t], a[1][0], a[1][1], a[1][2], a[1][3], b0, b1);
        }
    }
}

// ---------------------------------------------------------------------------
// k_attn1g: attn layer-1 via mma.sync. 12 M-tiles x 8 K-splits = 96 blocks.
// ---------------------------------------------------------------------------
__global__ void __launch_bounds__(256) k_attn1g(const float* __restrict__ X)
{
    extern __shared__ __align__(16) char smg[];
    char* Ab[2] = { smg, smg + ABUF };
    char* Wb[2] = { smg + 2 * ABUF, smg + 2 * ABUF + WBUF };
    uint32_t Wbu[2] = { smem_u32(Wb[0]), smem_u32(Wb[1]) };

    int tid = threadIdx.x, wid = tid >> 5, lane = tid & 31;
    int g = lane >> 2, tg = lane & 3;
    int wm = wid & 3, wn = wid >> 2;
    int mt = blockIdx.x >> 3, ksp = blockIdx.x & 7;
    int m0 = mt * 128;
    int wkoff = ksp * 576;

    int arow = tid >> 1, akh = tid & 1;
    int grow = m0 + arow;
    int si = grow >> 3, w = grow & 7;
    int b = si / SS;
    const float* Xp = X + ((size_t)(b * TT + d_starts[si] + w)) * EE
                        + ksp * 96 + akh * 16;
    int aoff = arow * 208 + akh * 96;

    float c[2][10][4];
    #pragma unroll
    for (int m2 = 0; m2 < 2; m2++)
        #pragma unroll
        for (int t = 0; t < 10; t++)
            #pragma unroll
            for (int q = 0; q < 4; q++) c[m2][t][q] = 0.f;

    float xr[16];
    cpw_generic(Wbu[0], (const char*)d_AWi, KA * 2, wkoff, tid);
    CP_COMMIT();
    {
        const float4* x4 = (const float4*)Xp;
        #pragma unroll
        for (int u = 0; u < 4; u++) {
            float4 a = x4[u];
            xr[4*u] = a.x; xr[4*u+1] = a.y; xr[4*u+2] = a.z; xr[4*u+3] = a.w;
        }
    }
    pack_store(Ab[0], aoff, xr);
    CP_WAIT0();
    __syncthreads();

    for (int ch = 0; ch < 3; ch++) {
        int buf = ch & 1, nb = buf ^ 1;
        bool more = (ch + 1 < 3);
        if (more) {
            cpw_generic(Wbu[nb], (const char*)d_AWi, KA * 2,
                        wkoff + (ch + 1) * 192, tid);
            CP_COMMIT();
            const float4* x4 = (const float4*)(Xp + (ch + 1) * 32);
            #pragma unroll
            for (int u = 0; u < 4; u++) {
                float4 a = x4[u];
                xr[4*u] = a.x; xr[4*u+1] = a.y; xr[4*u+2] = a.z; xr[4*u+3] = a.w;
            }
        }
        gemm_chunk(Ab[buf], Wb[buf], wm, wn, g, tg, c);
        if (more) pack_store(Ab[nb], aoff, xr);
        CP_WAIT0();
        __syncthreads();
    }

    float* Cd = d_ap + (size_t)ksp * NROW * 160;
    #pragma unroll
    for (int m2 = 0; m2 < 2; m2++) {
        int rowa = m0 + wm * 32 + m2 * 16 + g;
        #pragma unroll
        for (int t = 0; t < 10; t++) {
            int col = wn * 80 + 8 * t + tg * 2;
            *(float2*)&Cd[(size_t)rowa * 160 + col] = make_float2(c[m2][t][0], c[m2][t][1]);
            *(float2*)&Cd[(size_t)(rowa + 8) * 160 + col] = make_float2(c[m2][t][2], c[m2][t][3]);
        }
    }
}

// ---------------------------------------------------------------------------
__global__ void k_hred(const float* __restrict__ ab1) {
    int idx = blockIdx.x * blockDim.x + threadIdx.x;
    if (idx >= NROW * 160) return;
    int h = idx % 160;
    float v = 0.f;
    if (h < HH) {
        float s = ab1[h];
        #pragma unroll
        for (int ks = 0; ks < 8; ks++)
            s += d_ap[(size_t)ks * NROW * 160 + idx];
        v = fmaxf(s, 0.f);
    }
    d_h1[idx] = v;
}

// ---------------------------------------------------------------------------
__global__ void __launch_bounds__(256) k_attn2m(
    const float* __restrict__ aw2, const float* __restrict__ ab2,
    const float* __restrict__ aw3, const float* __restrict__ ab3)
{
    int r0 = blockIdx.x * 16;
    int tid = threadIdx.x;
    int jg = tid >> 5, hg = tid & 31;
    int h0 = 5 * hg;
    int kk2 = tid >> 4, hb2 = tid & 15;

    __shared__ __align__(16) float s1[16 * HS];
    __shared__ __align__(16) float ews[16 * HS];
    __shared__ float eps[16 * 18];

    for (int idx = tid; idx < 16 * 160; idx += 256) {
        int t = idx / 160, h = idx - (idx / 160) * 160;
        s1[t * HS + h] = d_h1[(size_t)(r0 + t) * 160 + h];
    }

    float acc2[2][5];
    #pragma unroll
    for (int rr = 0; rr < 2; rr++)
        #pragma unroll
        for (int q = 0; q < 5; q++) {
            int h = h0 + q;
            acc2[rr][q] = (h < HH) ? ab2[h] : 0.f;
        }

    float wpre[10];
    #pragma unroll
    for (int q = 0; q < 10; q++) {
        int h = hb2 + 16 * q;
        wpre[q] = (kk2 < HH && h < HH) ? aw2[kk2 * HH + h] : 0.f;
    }

    for (int k0 = 0; k0 < 160; k0 += 16) {
        #pragma unroll
        for (int q = 0; q < 10; q++) {
            int h = hb2 + 16 * q;
            if (h < 160) ews[kk2 * HS + h] = wpre[q];
        }
        eps[kk2 * 18 + hb2] = s1[hb2 * HS + k0 + kk2];
        __syncthreads();
        if (k0 + 16 < 160) {
            int kn = k0 + 16 + kk2;
            #pragma unroll
            for (int q = 0; q < 10; q++) {
                int h = hb2 + 16 * q;
                wpre[q] = (kn < HH && h < HH) ? aw2[kn * HH + h] : 0.f;
            }
        }
        #pragma unroll
        for (int kk = 0; kk < 16; kk++) {
            float p0 = eps[kk * 18 + 2 * jg];
            float p1 = eps[kk * 18 + 2 * jg + 1];
            const float* wr = &ews[kk * HS + h0];
            #pragma unroll
            for (int q = 0; q < 5; q++) {
                float w = wr[q];
                acc2[0][q] += p0 * w;
                acc2[1][q] += p1 * w;
            }
        }
        __syncthreads();
    }

    float part[2];
    #pragma unroll
    for (int rr = 0; rr < 2; rr++) {
        float s = 0.f;
        #pragma unroll
        for (int q = 0; q < 5; q++) {
            int h = h0 + q;
            if (h < HH) s += fmaxf(acc2[rr][q], 0.f) * aw3[h];
        }
        part[rr] = s;
    }
    #pragma unroll
    for (int rr = 0; rr < 2; rr++)
        #pragma unroll
        for (int off = 16; off > 0; off >>= 1)
            part[rr] += __shfl_xor_sync(0xffffffffu, part[rr], off);
    if (hg == 0) {
        d_at[r0 + 2 * jg + 0] = part[0] + ab3[0];
        d_at[r0 + 2 * jg + 1] = part[1] + ab3[0];
    }
}

// ---------------------------------------------------------------------------
__global__ void __launch_bounds__(256) k_gather(const float* __restrict__ X)
{
    int si = blockIdx.x / 3;
    int e = (blockIdx.x % 3) * 256 + threadIdx.x;
    int b = si / SS;
    __shared__ float atv[8];
    if (threadIdx.x < 8) atv[threadIdx.x] = d_at[si * 8 + threadIdx.x];
    __syncthreads();

    const float* Xb = X + ((size_t)(b * TT + d_starts[si])) * EE + e;
    float s = 0.f, x0 = 0.f, x7 = 0.f;
    #pragma unroll
    for (int w = 0; w < WW; w++) {
        float xv = Xb[w * EE];
        if (w == 0) x0 = xv;
        if (w == 7) x7 = xv;
        s += xv * atv[w];
    }
    float* gp = d_g + (size_t)si * E3;
    gp[e]          = x0;
    gp[EE + e]     = x7;
    gp[2 * EE + e] = s;
}

// ---------------------------------------------------------------------------
// k_termsg2: {Wa, Wb, mw1} GEMMs via mma.sync with in-kernel W split staging.
// grid = 72: mt(2) x mat(3) x ksp(12). 6 chunks of 32 orig-k each.
// ---------------------------------------------------------------------------
__global__ void __launch_bounds__(256) k_termsg2(
    const float* __restrict__ pw1, const float* __restrict__ mw1)
{
    extern __shared__ __align__(16) char smg[];
    char* Ab[2] = { smg, smg + ABUF };
    char* Wb[2] = { smg + 2 * ABUF, smg + 2 * ABUF + WBUF };

    int tid = threadIdx.x, wid = tid >> 5, lane = tid & 31;
    int g = lane >> 2, tg = lane & 3;
    int wm = wid & 3, wn = wid >> 2;
    int x = blockIdx.x;
    int mt = x & 1, mat = (x >> 1) % 3, ksp = x / 6;    // ksp 0..11
    int m0 = mt * 128;
    const float* Wm = (mat == 0) ? pw1 : (mat == 1 ? pw1 + (size_t)E3 * HH : mw1);
    int kbase = ksp * 192;

    // A staging
    int arow = tid >> 1, akh = tid & 1;
    int grow = m0 + arow;
    if (grow > NSPAN - 1) grow = NSPAN - 1;
    const float* Gp = d_g + (size_t)grow * E3 + kbase + akh * 16;
    int aoff = arow * 208 + akh * 96;

    // W staging map: 10 items of (n, kp) — kp = pair of orig-k
    int nW[10], kpW[10];
    #pragma unroll
    for (int v = 0; v < 10; v++) {
        int u = tid + 256 * v;
        nW[v] = u % 160;
        kpW[v] = u / 160;       // 0..15
    }

    float c[2][10][4];
    #pragma unroll
    for (int m2 = 0; m2 < 2; m2++)
        #pragma unroll
        for (int t = 0; t < 10; t++)
            #pragma unroll
            for (int q = 0; q < 4; q++) c[m2][t][q] = 0.f;

    float xr[16], wp0[10], wp1[10];

    // ---- prefetch chunk 0 ----
    {
        int k0 = kbase;
        #pragma unroll
        for (int v = 0; v < 10; v++) {
            int n = nW[v], k = k0 + 2 * kpW[v];
            bool ok = (n < HH);
            wp0[v] = ok ? Wm[(size_t)k * HH + n] : 0.f;
            wp1[v] = ok ? Wm[(size_t)(k + 1) * HH + n] : 0.f;
        }
        const float4* x4 = (const float4*)Gp;
        #pragma unroll
        for (int u = 0; u < 4; u++) {
            float4 a = x4[u];
            xr[4*u] = a.x; xr[4*u+1] = a.y; xr[4*u+2] = a.z; xr[4*u+3] = a.w;
        }
    }
    // stage chunk 0
    #pragma unroll
    for (int v = 0; v < 10; v++) {
        unsigned short h0s, l0s, h1s, l1s;
        split_bf16(wp0[v], h0s, l0s);
        split_bf16(wp1[v], h1s, l1s);
        uint32_t* wdst = (uint32_t*)(Wb[0] + nW[v] * 208 + 12 * kpW[v]);
        wdst[0] = (uint32_t)h0s | ((uint32_t)l0s << 16);
        wdst[1] = (uint32_t)h0s | ((uint32_t)h1s << 16);
        wdst[2] = (uint32_t)l1s | ((uint32_t)h1s << 16);
    }
    pack_store(Ab[0], aoff, xr);
    __syncthreads();

    for (int ch = 0; ch < 6; ch++) {
        int buf = ch & 1, nb = buf ^ 1;
        bool more = (ch + 1 < 6);
        if (more) {
            int k0 = kbase + (ch + 1) * 32;
            #pragma unroll
            for (int v = 0; v < 10; v++) {
                int n = nW[v], k = k0 + 2 * kpW[v];
                bool ok = (n < HH);
                wp0[v] = ok ? Wm[(size_t)k * HH + n] : 0.f;
                wp1[v] = ok ? Wm[(size_t)(k + 1) * HH + n] : 0.f;
            }
            const float4* x4 = (const float4*)(Gp + (ch + 1) * 32);
            #pragma unroll
            for (int u = 0; u < 4; u++) {
                float4 a = x4[u];
                xr[4*u] = a.x; xr[4*u+1] = a.y; xr[4*u+2] = a.z; xr[4*u+3] = a.w;
            }
        }
        gemm_chunk(Ab[buf], Wb[buf], wm, wn, g, tg, c);
        if (more) {
            #pragma unroll
            for (int v = 0; v < 10; v++) {
                unsigned short h0s, l0s, h1s, l1s;
                split_bf16(wp0[v], h0s, l0s);
                split_bf16(wp1[v], h1s, l1s);
                uint32_t* wdst = (uint32_t*)(Wb[nb] + nW[v] * 208 + 12 * kpW[v]);
                wdst[0] = (uint32_t)h0s | ((uint32_t)l0s << 16);
                wdst[1] = (uint32_t)h0s | ((uint32_t)h1s << 16);
                wdst[2] = (uint32_t)l1s | ((uint32_t)h1s << 16);
            }
            pack_store(Ab[nb], aoff, xr);
        }
        __syncthreads();
    }

    float* Cd = d_part + ((size_t)mat * 12 + ksp) * 256 * 160;
    #pragma unroll
    for (int m2 = 0; m2 < 2; m2++) {
        int rowa = m0 + wm * 32 + m2 * 16 + g;
        #pragma unroll
        for (int t = 0; t < 10; t++) {
            int col = wn * 80 + 8 * t + tg * 2;
            *(float2*)&Cd[(size_t)rowa * 160 + col] = make_float2(c[m2][t][0], c[m2][t][1]);
            *(float2*)&Cd[(size_t)(rowa + 8) * 160 + col] = make_float2(c[m2][t][2], c[m2][t][3]);
        }
    }
}

// ---------------------------------------------------------------------------
// k_redment: reduce 12 terms partials (A, Bt, m1) + mention MLP. 192 blocks.
// ---------------------------------------------------------------------------
__global__ void __launch_bounds__(160) k_redment(
    const float* __restrict__ mb1, const float* __restrict__ mw2,
    const float* __restrict__ mb2, const float* __restrict__ mw3,
    const float* __restrict__ mb3)
{
    int s = blockIdx.x;
    int tid = threadIdx.x;
    __shared__ float s1[HH];
    __shared__ float warpsum[8];

    if (tid < HH) {
        float a = 0.f, b = 0.f, m = 0.f;
        #pragma unroll
        for (int ks = 0; ks < 12; ks++) {
            a += d_part[(((size_t)0 * 12 + ks) * 256 + s) * 160 + tid];
            b += d_part[(((size_t)1 * 12 + ks) * 256 + s) * 160 + tid];
            m += d_part[(((size_t)2 * 12 + ks) * 256 + s) * 160 + tid];
        }
        d_A[s * HH + tid]  = a;
        d_Bt[s * HH + tid] = b;
        s1[tid] = fmaxf(m + mb1[tid], 0.f);
    }
    __syncthreads();
    float p = 0.f;
    if (tid < HH) {
        float v = mb2[tid];
        for (int k = 0; k < HH; k++) v += s1[k] * mw2[k * HH + tid];
        p = fmaxf(v, 0.f) * mw3[tid];
    }
    #pragma unroll
    for (int o = 16; o > 0; o >>= 1) p += __shfl_down_sync(0xffffffffu, p, o);
    if ((tid & 31) == 0) warpsum[tid >> 5] = p;
    __syncthreads();
    if (tid == 0) {
        float t = mb3[0];
        for (int w = 0; w < 5; w++) t += warpsum[w];
        d_ms[s] = t;
    }
}

// ---------------------------------------------------------------------------
// k_gemm: pair C-term via mma.sync (validated).
// ---------------------------------------------------------------------------
__device__ __forceinline__ void lda_pair(const float* gi, const float* gj,
                                         int ch, float* pv) {
    const float4* a4 = (const float4*)(gi + ch * 32);
    const float4* b4 = (const float4*)(gj + ch * 32);
    #pragma unroll
    for (int u = 0; u < 4; u++) {
        float4 a = a4[u], b = b4[u];
        pv[4*u+0] = a.x * b.x; pv[4*u+1] = a.y * b.y;
        pv[4*u+2] = a.z * b.z; pv[4*u+3] = a.w * b.w;
    }
}

__global__ void __launch_bounds__(256) k_gemm()
{
    extern __shared__ __align__(16) char smg[];
    char* Ab[2] = { smg, smg + ABUF };
    char* Wb[2] = { smg + 2 * ABUF, smg + 2 * ABUF + WBUF };
    uint32_t Wbu[2] = { smem_u32(Wb[0]), smem_u32(Wb[1]) };

    int tid = threadIdx.x, wid = tid >> 5, lane = tid & 31;
    int g = lane >> 2, tg = lane & 3;
    int wm = wid & 3, wn = wid >> 2;
    int mt = blockIdx.x >> 1, ksp = blockIdx.x & 1;
    int m0 = mt * 128;
    int wkoff = ksp * 3456 * 2;

    int arow = tid >> 1, akh = tid & 1;
    const float* gi = d_g + (size_t)d_pi[m0 + arow] * E3 + ksp * 1152 + akh * 16;
    const float* gj = d_g + (size_t)d_pj[m0 + arow] * E3 + ksp * 1152 + akh * 16;
    int aoff = arow * 208 + akh * 96;

    float c[2][10][4];
    #pragma unroll
    for (int m2 = 0; m2 < 2; m2++)
        #pragma unroll
        for (int t = 0; t < 10; t++)
            #pragma unroll
            for (int q = 0; q < 4; q++) c[m2][t][q] = 0.f;

    float pv[16];
    cpw_generic(Wbu[0], (const char*)d_Wi, KPR * 2, wkoff, tid);
    CP_COMMIT();
    lda_pair(gi, gj, 0, pv);
    pack_store(Ab[0], aoff, pv);
    CP_WAIT0();
    __syncthreads();

    for (int ch = 0; ch < NCHA2; ch++) {
        int buf = ch & 1, nb = buf ^ 1;
        bool more = (ch + 1 < NCHA2);
        if (more) {
            cpw_generic(Wbu[nb], (const char*)d_Wi, KPR * 2,
                        wkoff + (ch + 1) * 192, tid);
            CP_COMMIT();
            lda_pair(gi, gj, ch + 1, pv);
        }
        gemm_chunk(Ab[buf], Wb[buf], wm, wn, g, tg, c);
        if (more) pack_store(Ab[nb], aoff, pv);
        CP_WAIT0();
        __syncthreads();
    }

    float* Cd = d_Cg2[ksp];
    #pragma unroll
    for (int m2 = 0; m2 < 2; m2++) {
        int rowa = m0 + wm * 32 + m2 * 16 + g;
        #pragma unroll
        for (int t = 0; t < 10; t++) {
            int col = wn * 80 + 8 * t + tg * 2;
            *(float2*)&Cd[(size_t)rowa * 160 + col] = make_float2(c[m2][t][0], c[m2][t][1]);
            *(float2*)&Cd[(size_t)(rowa + 8) * 160 + col] = make_float2(c[m2][t][2], c[m2][t][3]);
        }
    }
}

// ---------------------------------------------------------------------------
// k_pairE: layer-1 epilogue -> split-bf16 A', tensor layer-2, fused layer-3.
// ---------------------------------------------------------------------------
__global__ void __launch_bounds__(256) k_pairE(
    const float* __restrict__ pb1, const float* __restrict__ pb2,
    const float* __restrict__ pw3, const float* __restrict__ pb3,
    float* __restrict__ out)
{
    extern __shared__ __align__(16) char smE[];
    unsigned short* A2 = (unsigned short*)smE;
    char* W2b[2] = { smE + A2BYTES, smE + A2BYTES + W2CB };
    uint32_t W2u[2] = { smem_u32(W2b[0]), smem_u32(W2b[1]) };
    __shared__ int pis[32], pjs[32];
    __shared__ float rsum[64][2];

    int r0 = blockIdx.x * 32;
    int tid = threadIdx.x;
    int jg = tid >> 5;
    int hg = tid & 31;
    int h0 = 5 * hg;
    int lane = tid & 31, wid = tid >> 5;
    int g = lane >> 2, tg = lane & 3;
    int wm = wid & 3, wn = wid >> 2;

    if (tid < 32) { pis[tid] = d_pi[r0 + tid]; pjs[tid] = d_pj[r0 + tid]; }

    #pragma unroll
    for (int v = 0; v < 3; v++) {
        int unit = tid + 256 * v;
        if (unit < 640) {
            int n = unit >> 2, q = unit & 3;
            CP_ASYNC16(W2u[0] + n * 80 + q * 16,
                       (const char*)d_W2i + (size_t)n * 960 + q * 16);
        }
    }
    CP_COMMIT();

    {
        uint4 z = make_uint4(0, 0, 0, 0);
        uint4* a4 = (uint4*)A2;
        for (int idx = tid; idx < A2BYTES / 16; idx += 256) a4[idx] = z;
    }
    __syncthreads();

    #pragma unroll
    for (int jj = 0; jj < 4; jj++) {
        int t = 4 * jg + jj;
        int r = r0 + t;
        int pi = pis[t], pj = pjs[t];
        #pragma unroll
        for (int q = 0; q < 5; q++) {
            int h = h0 + q;
            if (h < HH) {
                size_t idx = (size_t)r * 160 + h;
                float cc = d_Cg2[0][idx] + d_Cg2[1][idx] + pb1[h];
                float vf = fmaxf(cc + d_A[pi * HH + h] + d_Bt[pj * HH + h], 0.f);
                float vt = fmaxf(cc + d_A[pj * HH + h] + d_Bt[pi * HH + h], 0.f);
                unsigned short hu, lu;
                split_bf16(vf, hu, lu);
                unsigned short* p = A2 + (size_t)t * 488 + 3 * h;
                p[0] = hu; p[1] = hu; p[2] = lu;
                split_bf16(vt, hu, lu);
                unsigned short* p2 = A2 + (size_t)(32 + t) * 488 + 3 * h;
                p2[0] = hu; p2[1] = hu; p2[2] = lu;
            }
        }
    }
    CP_WAIT0();
    __syncthreads();

    float c[10][4];
    #pragma unroll
    for (int t = 0; t < 10; t++)
        #pragma unroll
        for (int q = 0; q < 4; q++) c[t][q] = 0.f;

    for (int ch = 0; ch < 15; ch++) {
        int buf = ch & 1, nb = buf ^ 1;
        bool more = (ch + 1 < 15);
        if (more) {
            #pragma unroll
            for (int v = 0; v < 3; v++) {
                int unit = tid + 256 * v;
                if (unit < 640) {
                    int n = unit >> 2, q = unit & 3;
                    CP_ASYNC16(W2u[nb] + n * 80 + q * 16,
                               (const char*)d_W2i + (size_t)n * 960
                               + (ch + 1) * 64 + q * 16);
                }
            }
            CP_COMMIT();
        }
        const char* W = (const char*)W2b[buf];
        const char* A = (const char*)A2;
        #pragma unroll
        for (int s = 0; s < 2; s++) {
            int k0 = ch * 32 + s * 16;
            int ab = (16 * wm + g) * A2RS + (k0 + tg * 2) * 2;
            uint32_t a0 = *(const uint32_t*)(A + ab);
            uint32_t a1 = *(const uint32_t*)(A + ab + 8 * A2RS);
            uint32_t a2 = *(const uint32_t*)(A + ab + 16);
            uint32_t a3 = *(const uint32_t*)(A + ab + 8 * A2RS + 16);
            #pragma unroll
            for (int t = 0; t < 10; t++) {
                int wo = (wn * 80 + 8 * t + g) * 80 + s * 32 + tg * 4;
                uint32_t b0 = *(const uint32_t*)(W + wo);
                uint32_t b1 = *(const uint32_t*)(W + wo + 16);
                mma16816(c[t], a0, a1, a2, a3, b0, b1);
            }
        }
        if (more) { CP_WAIT0(); }
        __syncthreads();
    }

    float sg = 0.f, sg8 = 0.f;
    #pragma unroll
    for (int t = 0; t < 10; t++) {
        int n0 = wn * 80 + 8 * t + tg * 2;
        int n1 = n0 + 1;
        float b20 = (n0 < HH) ? pb2[n0] : 0.f;
        float b21 = (n1 < HH) ? pb2[n1] : 0.f;
        float w30 = (n0 < HH) ? pw3[n0] : 0.f;
        float w31 = (n1 < HH) ? pw3[n1] : 0.f;
        sg  += fmaxf(c[t][0] + b20, 0.f) * w30 + fmaxf(c[t][1] + b21, 0.f) * w31;
        sg8 += fmaxf(c[t][2] + b20, 0.f) * w30 + fmaxf(c[t][3] + b21, 0.f) * w31;
    }
    sg  += __shfl_xor_sync(0xffffffffu, sg, 1);
    sg  += __shfl_xor_sync(0xffffffffu, sg, 2);
    sg8 += __shfl_xor_sync(0xffffffffu, sg8, 1);
    sg8 += __shfl_xor_sync(0xffffffffu, sg8, 2);
    if (tg == 0) {
        rsum[16 * wm + g][wn] = sg;
        rsum[16 * wm + g + 8][wn] = sg8;
    }
    __syncthreads();

    if (tid < 64) {
        int row = tid;
        int t = row & 31;
        int fi, se;
        if (row < 32) { fi = pis[t]; se = pjs[t]; }
        else          { fi = pjs[t]; se = pis[t]; }
        float sc = rsum[row][0] + rsum[row][1] + pb3[0];
        float v = ((d_ms[fi] + d_ms[se]) + sc) * (1.f / 3.f);
        v = fminf(fmaxf(v, 0.f), 1.f);
        out[(size_t)fi * SS + (se % SS)] = v;
    }
}

// ---------------------------------------------------------------------------
extern "C" void kernel_launch(void* const* d_in, const int* in_sizes, int n_in,
                              void* d_out, int out_size)
{
    const float* X   = (const float*)d_in[0];
    const void*  sp  = d_in[1];
    const float* aw1 = (const float*)d_in[2];
    const float* ab1 = (const float*)d_in[3];
    const float* aw2 = (const float*)d_in[4];
    const float* ab2 = (const float*)d_in[5];
    const float* aw3 = (const float*)d_in[6];
    const float* ab3 = (const float*)d_in[7];
    const float* mw1 = (const float*)d_in[8];
    const float* mb1 = (const float*)d_in[9];
    const float* mw2 = (const float*)d_in[10];
    const float* mb2 = (const float*)d_in[11];
    const float* mw3 = (const float*)d_in[12];
    const float* mb3 = (const float*)d_in[13];
    const float* pw1 = (const float*)d_in[14];
    const float* pb1 = (const float*)d_in[15];
    const float* pw2 = (const float*)d_in[16];
    const float* pb2 = (const float*)d_in[17];
    const float* pw3 = (const float*)d_in[18];
    const float* pb3 = (const float*)d_in[19];
    float* out = (float*)d_out;

    cudaFuncSetAttribute(k_gemm, cudaFuncAttributeMaxDynamicSharedMemorySize,
                         SMEMG);
    cudaFuncSetAttribute(k_attn1g, cudaFuncAttributeMaxDynamicSharedMemorySize,
                         SMEMG);
    cudaFuncSetAttribute(k_termsg2, cudaFuncAttributeMaxDynamicSharedMemorySize,
                         SMEMG);
    cudaFuncSetAttribute(k_pairE, cudaFuncAttributeMaxDynamicSharedMemorySize,
                         SMEMPE);

    const int wtot = 160 * (E3 + 768 + 160);
    k_prep0<<<73, 256>>>(sp);
    k_wprep<<<(wtot + 255) / 256, 256>>>(pw1, aw1, pw2);
    k_attn1g<<<96, 256, SMEMG>>>(X);
    k_hred<<<(NROW * 160 + 255) / 256, 256>>>(ab1);
    k_attn2m<<<96, 256>>>(aw2, ab2, aw3, ab3);
    k_gather<<<NSPAN * 3, 256>>>(X);
    k_termsg2<<<72, 256, SMEMG>>>(pw1, mw1);
    k_redment<<<NSPAN, 160>>>(mb1, mw2, mb2, mw3, mb3);
    k_gemm<<<146, 256, SMEMG>>>();
    k_pairE<<<NPAIR / 32, 256, SMEMPE>>>(pb1, pb2, pw3, pb3, out);
}

// round 16
// speedup vs baseline: 1.0773x; 1.0773x over previous
#include <cuda_runtime.h>
#include <cuda_bf16.h>
#include <cstdint>

#define BB 2
#define TT 2048
#define EE 768
#define SS 96
#define HH 150
#define HS 168
#define WW 8
#define E3 2304
#define NSPAN (BB*SS)      // 192
#define NROW (NSPAN*WW)    // 1536
#define NPAIR 9312
#define NPAIRP 9344        // 73*128
#define KPR 6912           // 3*E3 interleaved split K
#define KA 2304            // 3*768
#define K2 480             // 3*160
#define NCHA2 36
#define ABUF 26624         // 128 rows * 208 B
#define WBUF 33280         // 160 rows * 208 B
#define SMEMG (2*ABUF + 2*WBUF)        // 119808
#define A2RS 976
#define A2BYTES (64*A2RS)              // 62464
#define W2CB 12800
#define SMEMPE (A2BYTES + 2*W2CB)      // 88064

// -------- device scratch --------
__device__ int   d_starts[NSPAN];
__device__ __align__(16) float d_g[NSPAN * E3];
__device__ float d_part[3 * 16 * NSPAN * HH];
__device__ float d_ap[8 * NROW * 160];
__device__ float d_at[NROW];
__device__ float d_A[NSPAN * HH];
__device__ float d_Bt[NSPAN * HH];
__device__ float d_ms[NSPAN];
__device__ int   d_pi[NPAIRP], d_pj[NPAIRP];
__device__ __align__(16) __nv_bfloat16 d_Wi[160 * KPR];
__device__ __align__(16) __nv_bfloat16 d_AWi[160 * KA];
__device__ __align__(16) __nv_bfloat16 d_W2i[160 * K2];
__device__ float d_Cg2[2][(size_t)NPAIRP * 160];

// -------- generic-PTX helpers --------
__device__ __forceinline__ uint32_t smem_u32(const void* p) {
    uint32_t a;
    asm("{ .reg .u64 t; cvta.to.shared.u64 t, %1; cvt.u32.u64 %0, t; }"
        : "=r"(a) : "l"(p));
    return a;
}
#define CP_ASYNC16(dst, src) \
    asm volatile("cp.async.cg.shared.global [%0], [%1], 16;" \
                 :: "r"(dst), "l"(src) : "memory")
#define CP_COMMIT() asm volatile("cp.async.commit_group;" ::: "memory")
#define CP_WAIT0()  asm volatile("cp.async.wait_group 0;" ::: "memory")

__device__ __forceinline__ void mma16816(float c[4], uint32_t a0, uint32_t a1,
                                         uint32_t a2, uint32_t a3,
                                         uint32_t b0, uint32_t b1) {
    asm volatile(
        "mma.sync.aligned.m16n8k16.row.col.f32.bf16.bf16.f32 "
        "{%0,%1,%2,%3}, {%4,%5,%6,%7}, {%8,%9}, {%0,%1,%2,%3};"
        : "+f"(c[0]), "+f"(c[1]), "+f"(c[2]), "+f"(c[3])
        : "r"(a0), "r"(a1), "r"(a2), "r"(a3), "r"(b0), "r"(b1));
}

__device__ __forceinline__ void split_bf16(float p, unsigned short& hu,
                                           unsigned short& lu) {
    asm("cvt.rn.bf16.f32 %0, %1;" : "=h"(hu) : "f"(p));
    float hf = __uint_as_float(((uint32_t)hu) << 16);
    float l = p - hf;
    asm("cvt.rn.bf16.f32 %0, %1;" : "=h"(lu) : "f"(l));
}

// ---------------------------------------------------------------------------
__global__ void k_prep0(const void* sp) {
    if (blockIdx.x == 72) {
        __shared__ int is64;
        if (threadIdx.x == 0) {
            const int* w32 = (const int*)sp;
            int z = 1;
            for (int i = 1; i < 64; i += 2) if (w32[i] != 0) { z = 0; break; }
            is64 = z;
        }
        __syncthreads();
        int i = threadIdx.x;
        if (i < NSPAN) {
            if (is64) d_starts[i] = (int)((const long long*)sp)[i];
            else      d_starts[i] = ((const int*)sp)[i];
        }
        return;
    }
    int idx = blockIdx.x * 256 + threadIdx.x;
    int b = idx / (SS * SS), r = idx % (SS * SS);
    int i = r / SS, j = r % SS;
    if (j >= i) {
        int row = b * 4656 + i * SS - i * (i - 1) / 2 + (j - i);
        d_pi[row] = b * SS + i;
        d_pj[row] = b * SS + j;
    }
    if (idx < NPAIRP - NPAIR) {
        d_pi[NPAIR + idx] = NSPAN - 1;
        d_pj[NPAIR + idx] = NSPAN - 1;
    }
}

// ---------------------------------------------------------------------------
// k_wprep: interleaved bf16 splits: Wc, aw1, pw2.  Pattern: [hi, lo, hi]
// ---------------------------------------------------------------------------
__global__ void k_wprep(const float* __restrict__ pw1,
                        const float* __restrict__ aw1,
                        const float* __restrict__ pw2) {
    int idx = blockIdx.x * blockDim.x + threadIdx.x;
    const int S0 = 160 * E3;
    const int S1 = 160 * 768;
    const int S2 = 160 * 160;
    if (idx >= S0 + S1 + S2) return;
    float w = 0.f;
    unsigned short* dst;
    if (idx < S0) {
        int n = idx / E3, k = idx % E3;
        if (n < HH) w = pw1[(size_t)2 * E3 * HH + (size_t)k * HH + n];
        dst = (unsigned short*)d_Wi + (size_t)n * KPR + 3 * k;
    } else if (idx < S0 + S1) {
        int i2 = idx - S0;
        int n = i2 / 768, k = i2 % 768;
        if (n < HH) w = aw1[(size_t)k * HH + n];
        dst = (unsigned short*)d_AWi + (size_t)n * KA + 3 * k;
    } else {
        int i3 = idx - S0 - S1;
        int n = i3 / 160, k = i3 % 160;
        if (n < HH && k < HH) w = pw2[(size_t)k * HH + n];
        dst = (unsigned short*)d_W2i + (size_t)n * K2 + 3 * k;
    }
    unsigned short hu, lu;
    split_bf16(w, hu, lu);
    dst[0] = hu; dst[1] = lu; dst[2] = hu;
}

// ---------------------------------------------------------------------------
__device__ __forceinline__ void cpw_generic(uint32_t wdst, const char* srcbase,
                                            size_t rstride, int choff, int tid) {
    #pragma unroll
    for (int v = 0; v < 2; v++) {
        int unit = tid + 256 * v;
        if (unit < 320) {
            int n = unit >> 1, kh = unit & 1;
            const char* src = srcbase + (size_t)n * rstride + choff + kh * 96;
            uint32_t dst = wdst + n * 208 + kh * 96;
            #pragma unroll
            for (int q = 0; q < 6; q++)
                CP_ASYNC16(dst + q * 16, src + q * 16);
        }
    }
}

__device__ __forceinline__ void pack_store(char* dst, int aoff,
                                           const float* pv) {
    unsigned short us[48];
    #pragma unroll
    for (int k = 0; k < 16; k++) {
        unsigned short hu, lu;
        split_bf16(pv[k], hu, lu);
        us[3*k+0] = hu; us[3*k+1] = hu; us[3*k+2] = lu;
    }
    uint32_t u[24];
    #pragma unroll
    for (int j = 0; j < 24; j++)
        u[j] = (uint32_t)us[2*j] | ((uint32_t)us[2*j+1] << 16);
    uint4* d = (uint4*)(dst + aoff);
    d[0] = make_uint4(u[0],  u[1],  u[2],  u[3]);
    d[1] = make_uint4(u[4],  u[5],  u[6],  u[7]);
    d[2] = make_uint4(u[8],  u[9],  u[10], u[11]);
    d[3] = make_uint4(u[12], u[13], u[14], u[15]);
    d[4] = make_uint4(u[16], u[17], u[18], u[19]);
    d[5] = make_uint4(u[20], u[21], u[22], u[23]);
}

// ---------------------------------------------------------------------------
__device__ __forceinline__ void gemm_chunk(const char* A, const char* W,
                                           int wm, int wn, int g, int tg,
                                           float c[2][10][4]) {
    #pragma unroll
    for (int s = 0; s < 6; s++) {
        uint32_t a[2][4];
        #pragma unroll
        for (int m2 = 0; m2 < 2; m2++) {
            int r0 = (wm * 32 + m2 * 16 + g) * 208 + s * 32 + tg * 4;
            a[m2][0] = *(const uint32_t*)(A + r0);
            a[m2][1] = *(const uint32_t*)(A + r0 + 8 * 208);
            a[m2][2] = *(const uint32_t*)(A + r0 + 16);
            a[m2][3] = *(const uint32_t*)(A + r0 + 8 * 208 + 16);
        }
        #pragma unroll
        for (int t = 0; t < 10; t++) {
            int wo = (wn * 80 + 8 * t + g) * 208 + s * 32 + tg * 4;
            uint32_t b0 = *(const uint32_t*)(W + wo);
            uint32_t b1 = *(const uint32_t*)(W + wo + 16);
            mma16816(c[0][t], a[0][0], a[0][1], a[0][2], a[0][3], b0, b1);
            mma16816(c[1][t], a[1][0], a[1][1], a[1][2], a[1][3], b0, b1);
        }
    }
}

// ---------------------------------------------------------------------------
// k_attn1g: attn layer-1 via mma.sync. 12 M-tiles x 8 K-splits = 96 blocks.
// ---------------------------------------------------------------------------
__global__ void __launch_bounds__(256) k_attn1g(const float* __restrict__ X)
{
    extern __shared__ __align__(16) char smg[];
    char* Ab[2] = { smg, smg + ABUF };
    char* Wb[2] = { smg + 2 * ABUF, smg + 2 * ABUF + WBUF };
    uint32_t Wbu[2] = { smem_u32(Wb[0]), smem_u32(Wb[1]) };

    int tid = threadIdx.x, wid = tid >> 5, lane = tid & 31;
    int g = lane >> 2, tg = lane & 3;
    int wm = wid & 3, wn = wid >> 2;
    int mt = blockIdx.x >> 3, ksp = blockIdx.x & 7;
    int m0 = mt * 128;
    int wkoff = ksp * 576;

    int arow = tid >> 1, akh = tid & 1;
    int grow = m0 + arow;
    int si = grow >> 3, w = grow & 7;
    int b = si / SS;
    const float* Xp = X + ((size_t)(b * TT + d_starts[si] + w)) * EE
                        + ksp * 96 + akh * 16;
    int aoff = arow * 208 + akh * 96;

    float c[2][10][4];
    #pragma unroll
    for (int m2 = 0; m2 < 2; m2++)
        #pragma unroll
        for (int t = 0; t < 10; t++)
            #pragma unroll
            for (int q = 0; q < 4; q++) c[m2][t][q] = 0.f;

    float xr[16];
    cpw_generic(Wbu[0], (const char*)d_AWi, KA * 2, wkoff, tid);
    CP_COMMIT();
    {
        const float4* x4 = (const float4*)Xp;
        #pragma unroll
        for (int u = 0; u < 4; u++) {
            float4 a = x4[u];
            xr[4*u] = a.x; xr[4*u+1] = a.y; xr[4*u+2] = a.z; xr[4*u+3] = a.w;
        }
    }
    pack_store(Ab[0], aoff, xr);
    CP_WAIT0();
    __syncthreads();

    for (int ch = 0; ch < 3; ch++) {
        int buf = ch & 1, nb = buf ^ 1;
        bool more = (ch + 1 < 3);
        if (more) {
            cpw_generic(Wbu[nb], (const char*)d_AWi, KA * 2,
                        wkoff + (ch + 1) * 192, tid);
            CP_COMMIT();
            const float4* x4 = (const float4*)(Xp + (ch + 1) * 32);
            #pragma unroll
            for (int u = 0; u < 4; u++) {
                float4 a = x4[u];
                xr[4*u] = a.x; xr[4*u+1] = a.y; xr[4*u+2] = a.z; xr[4*u+3] = a.w;
            }
        }
        gemm_chunk(Ab[buf], Wb[buf], wm, wn, g, tg, c);
        if (more) pack_store(Ab[nb], aoff, xr);
        CP_WAIT0();
        __syncthreads();
    }

    float* Cd = d_ap + (size_t)ksp * NROW * 160;
    #pragma unroll
    for (int m2 = 0; m2 < 2; m2++) {
        int rowa = m0 + wm * 32 + m2 * 16 + g;
        #pragma unroll
        for (int t = 0; t < 10; t++) {
            int col = wn * 80 + 8 * t + tg * 2;
            *(float2*)&Cd[(size_t)rowa * 160 + col] = make_float2(c[m2][t][0], c[m2][t][1]);
            *(float2*)&Cd[(size_t)(rowa + 8) * 160 + col] = make_float2(c[m2][t][2], c[m2][t][3]);
        }
    }
}

// ---------------------------------------------------------------------------
// k_attn2m: fused 8-partial reduce + attn layers 2,3. 96 blocks x 16 rows.
// ---------------------------------------------------------------------------
__global__ void __launch_bounds__(256) k_attn2m(
    const float* __restrict__ ab1,
    const float* __restrict__ aw2, const float* __restrict__ ab2,
    const float* __restrict__ aw3, const float* __restrict__ ab3)
{
    int r0 = blockIdx.x * 16;
    int tid = threadIdx.x;
    int jg = tid >> 5, hg = tid & 31;
    int h0 = 5 * hg;
    int kk2 = tid >> 4, hb2 = tid & 15;

    __shared__ __align__(16) float s1[16 * HS];
    __shared__ __align__(16) float ews[16 * HS];
    __shared__ float eps[16 * 18];

    for (int idx = tid; idx < 16 * 160; idx += 256) {
        int t = idx / 160, h = idx - (idx / 160) * 160;
        float v = 0.f;
        if (h < HH) {
            float s = ab1[h];
            size_t base = (size_t)(r0 + t) * 160 + h;
            #pragma unroll
            for (int ks = 0; ks < 8; ks++)
                s += d_ap[(size_t)ks * NROW * 160 + base];
            v = fmaxf(s, 0.f);
        }
        s1[t * HS + h] = v;
    }
    __syncthreads();   // s1 must be fully staged before any thread reads it

    float acc2[2][5];
    #pragma unroll
    for (int rr = 0; rr < 2; rr++)
        #pragma unroll
        for (int q = 0; q < 5; q++) {
            int h = h0 + q;
            acc2[rr][q] = (h < HH) ? ab2[h] : 0.f;
        }

    float wpre[10];
    #pragma unroll
    for (int q = 0; q < 10; q++) {
        int h = hb2 + 16 * q;
        wpre[q] = (kk2 < HH && h < HH) ? aw2[kk2 * HH + h] : 0.f;
    }

    for (int k0 = 0; k0 < 160; k0 += 16) {
        #pragma unroll
        for (int q = 0; q < 10; q++) {
            int h = hb2 + 16 * q;
            if (h < 160) ews[kk2 * HS + h] = wpre[q];
        }
        eps[kk2 * 18 + hb2] = s1[hb2 * HS + k0 + kk2];
        __syncthreads();
        if (k0 + 16 < 160) {
            int kn = k0 + 16 + kk2;
            #pragma unroll
            for (int q = 0; q < 10; q++) {
                int h = hb2 + 16 * q;
                wpre[q] = (kn < HH && h < HH) ? aw2[kn * HH + h] : 0.f;
            }
        }
        #pragma unroll
        for (int kk = 0; kk < 16; kk++) {
            float p0 = eps[kk * 18 + 2 * jg];
            float p1 = eps[kk * 18 + 2 * jg + 1];
            const float* wr = &ews[kk * HS + h0];
            #pragma unroll
            for (int q = 0; q < 5; q++) {
                float w = wr[q];
                acc2[0][q] += p0 * w;
                acc2[1][q] += p1 * w;
            }
        }
        __syncthreads();
    }

    float part[2];
    #pragma unroll
    for (int rr = 0; rr < 2; rr++) {
        float s = 0.f;
        #pragma unroll
        for (int q = 0; q < 5; q++) {
            int h = h0 + q;
            if (h < HH) s += fmaxf(acc2[rr][q], 0.f) * aw3[h];
        }
        part[rr] = s;
    }
    #pragma unroll
    for (int rr = 0; rr < 2; rr++)
        #pragma unroll
        for (int off = 16; off > 0; off >>= 1)
            part[rr] += __shfl_xor_sync(0xffffffffu, part[rr], off);
    if (hg == 0) {
        d_at[r0 + 2 * jg + 0] = part[0] + ab3[0];
        d_at[r0 + 2 * jg + 1] = part[1] + ab3[0];
    }
}

// ---------------------------------------------------------------------------
__global__ void __launch_bounds__(256) k_gather(const float* __restrict__ X)
{
    int si = blockIdx.x / 3;
    int e = (blockIdx.x % 3) * 256 + threadIdx.x;
    int b = si / SS;
    __shared__ float atv[8];
    if (threadIdx.x < 8) atv[threadIdx.x] = d_at[si * 8 + threadIdx.x];
    __syncthreads();

    const float* Xb = X + ((size_t)(b * TT + d_starts[si])) * EE + e;
    float s = 0.f, x0 = 0.f, x7 = 0.f;
    #pragma unroll
    for (int w = 0; w < WW; w++) {
        float xv = Xb[w * EE];
        if (w == 0) x0 = xv;
        if (w == 7) x7 = xv;
        s += xv * atv[w];
    }
    float* gp = d_g + (size_t)si * E3;
    gp[e]          = x0;
    gp[EE + e]     = x7;
    gp[2 * EE + e] = s;
}

// ---------------------------------------------------------------------------
// k_terms: fp32 tile GEMM (validated). grid 288.
// ---------------------------------------------------------------------------
__global__ void __launch_bounds__(256) k_terms(
    const float* __restrict__ pw1, const float* __restrict__ mw1)
{
    int x = blockIdx.x;
    int sc  = x % 6;
    int mat = (x / 6) % 3;
    int ks  = x / 18;
    const float* Wm = (mat == 0) ? pw1 : (mat == 1 ? pw1 + (size_t)E3 * HH : mw1);
    int s0 = sc * 32;
    int kbase = ks * 144;
    int tid = threadIdx.x;
    int jg = tid >> 5;
    int hg = tid & 31;
    int h0 = 5 * hg;
    int kk2 = tid >> 4;
    int hb2 = tid & 15;

    __shared__ __align__(16) float wst[16 * HS];
    __shared__ __align__(16) float pst[16 * 36];

    float acc[4][5];
    #pragma unroll
    for (int jj = 0; jj < 4; jj++)
        #pragma unroll
        for (int q = 0; q < 5; q++) acc[jj][q] = 0.f;

    for (int kc = 0; kc < 144; kc += 16) {
        int k0 = kbase + kc;
        __syncthreads();
        #pragma unroll
        for (int q = 0; q < 10; q++) {
            int h = hb2 + 16 * q;
            if (h < 160)
                wst[kk2 * HS + h] = (h < HH) ? Wm[(size_t)(k0 + kk2) * HH + h] : 0.f;
        }
        #pragma unroll
        for (int r = 0; r < 2; r++) {
            int idx = tid + 256 * r;
            int t = idx >> 4, kk = idx & 15;
            pst[kk * 36 + t] = d_g[(size_t)(s0 + t) * E3 + k0 + kk];
        }
        __syncthreads();
        #pragma unroll
        for (int kk = 0; kk < 16; kk++) {
            float4 p = *(const float4*)&pst[kk * 36 + 4 * jg];
            const float* wr = &wst[kk * HS + h0];
            float w0 = wr[0], w1 = wr[1], w2 = wr[2], w3 = wr[3], w4 = wr[4];
            acc[0][0] += p.x * w0; acc[0][1] += p.x * w1; acc[0][2] += p.x * w2;
            acc[0][3] += p.x * w3; acc[0][4] += p.x * w4;
            acc[1][0] += p.y * w0; acc[1][1] += p.y * w1; acc[1][2] += p.y * w2;
            acc[1][3] += p.y * w3; acc[1][4] += p.y * w4;
            acc[2][0] += p.z * w0; acc[2][1] += p.z * w1; acc[2][2] += p.z * w2;
            acc[2][3] += p.z * w3; acc[2][4] += p.z * w4;
            acc[3][0] += p.w * w0; acc[3][1] += p.w * w1; acc[3][2] += p.w * w2;
            acc[3][3] += p.w * w3; acc[3][4] += p.w * w4;
        }
    }
    #pragma unroll
    for (int jj = 0; jj < 4; jj++) {
        int t = 4 * jg + jj;
        float* op = d_part + (((size_t)mat * 16 + ks) * NSPAN + s0 + t) * HH;
        #pragma unroll
        for (int q = 0; q < 5; q++) {
            int h = h0 + q;
            if (h < HH) op[h] = acc[jj][q];
        }
    }
}

// ---------------------------------------------------------------------------
// k_redment: reduce 16 partials (A, Bt, m1) + mention MLP. 192 blocks.
// ---------------------------------------------------------------------------
__global__ void __launch_bounds__(160) k_redment(
    const float* __restrict__ mb1, const float* __restrict__ mw2,
    const float* __restrict__ mb2, const float* __restrict__ mw3,
    const float* __restrict__ mb3)
{
    int s = blockIdx.x;
    int tid = threadIdx.x;
    __shared__ float s1[HH];
    __shared__ float warpsum[8];

    if (tid < HH) {
        float a = 0.f, b = 0.f, m = 0.f;
        #pragma unroll
        for (int ks = 0; ks < 16; ks++) {
            a += d_part[(((size_t)0 * 16 + ks) * NSPAN + s) * HH + tid];
            b += d_part[(((size_t)1 * 16 + ks) * NSPAN + s) * HH + tid];
            m += d_part[(((size_t)2 * 16 + ks) * NSPAN + s) * HH + tid];
        }
        d_A[s * HH + tid]  = a;
        d_Bt[s * HH + tid] = b;
        s1[tid] = fmaxf(m + mb1[tid], 0.f);
    }
    __syncthreads();
    float p = 0.f;
    if (tid < HH) {
        float v = mb2[tid];
        for (int k = 0; k < HH; k++) v += s1[k] * mw2[k * HH + tid];
        p = fmaxf(v, 0.f) * mw3[tid];
    }
    #pragma unroll
    for (int o = 16; o > 0; o >>= 1) p += __shfl_down_sync(0xffffffffu, p, o);
    if ((tid & 31) == 0) warpsum[tid >> 5] = p;
    __syncthreads();
    if (tid == 0) {
        float t = mb3[0];
        for (int w = 0; w < 5; w++) t += warpsum[w];
        d_ms[s] = t;
    }
}

// ---------------------------------------------------------------------------
// k_gemm: pair C-term via mma.sync (validated).
// ---------------------------------------------------------------------------
__device__ __forceinline__ void lda_pair(const float* gi, const float* gj,
                                         int ch, float* pv) {
    const float4* a4 = (const float4*)(gi + ch * 32);
    const float4* b4 = (const float4*)(gj + ch * 32);
    #pragma unroll
    for (int u = 0; u < 4; u++) {
        float4 a = a4[u], b = b4[u];
        pv[4*u+0] = a.x * b.x; pv[4*u+1] = a.y * b.y;
        pv[4*u+2] = a.z * b.z; pv[4*u+3] = a.w * b.w;
    }
}

__global__ void __launch_bounds__(256) k_gemm()
{
    extern __shared__ __align__(16) char smg[];
    char* Ab[2] = { smg, smg + ABUF };
    char* Wb[2] = { smg + 2 * ABUF, smg + 2 * ABUF + WBUF };
    uint32_t Wbu[2] = { smem_u32(Wb[0]), smem_u32(Wb[1]) };

    int tid = threadIdx.x, wid = tid >> 5, lane = tid & 31;
    int g = lane >> 2, tg = lane & 3;
    int wm = wid & 3, wn = wid >> 2;
    int mt = blockIdx.x >> 1, ksp = blockIdx.x & 1;
    int m0 = mt * 128;
    int wkoff = ksp * 3456 * 2;

    int arow = tid >> 1, akh = tid & 1;
    const float* gi = d_g + (size_t)d_pi[m0 + arow] * E3 + ksp * 1152 + akh * 16;
    const float* gj = d_g + (size_t)d_pj[m0 + arow] * E3 + ksp * 1152 + akh * 16;
    int aoff = arow * 208 + akh * 96;

    float c[2][10][4];
    #pragma unroll
    for (int m2 = 0; m2 < 2; m2++)
        #pragma unroll
        for (int t = 0; t < 10; t++)
            #pragma unroll
            for (int q = 0; q < 4; q++) c[m2][t][q] = 0.f;

    float pv[16];
    cpw_generic(Wbu[0], (const char*)d_Wi, KPR * 2, wkoff, tid);
    CP_COMMIT();
    lda_pair(gi, gj, 0, pv);
    pack_store(Ab[0], aoff, pv);
    CP_WAIT0();
    __syncthreads();

    for (int ch = 0; ch < NCHA2; ch++) {
        int buf = ch & 1, nb = buf ^ 1;
        bool more = (ch + 1 < NCHA2);
        if (more) {
            cpw_generic(Wbu[nb], (const char*)d_Wi, KPR * 2,
                        wkoff + (ch + 1) * 192, tid);
            CP_COMMIT();
            lda_pair(gi, gj, ch + 1, pv);
        }
        gemm_chunk(Ab[buf], Wb[buf], wm, wn, g, tg, c);
        if (more) pack_store(Ab[nb], aoff, pv);
        CP_WAIT0();
        __syncthreads();
    }

    float* Cd = d_Cg2[ksp];
    #pragma unroll
    for (int m2 = 0; m2 < 2; m2++) {
        int rowa = m0 + wm * 32 + m2 * 16 + g;
        #pragma unroll
        for (int t = 0; t < 10; t++) {
            int col = wn * 80 + 8 * t + tg * 2;
            *(float2*)&Cd[(size_t)rowa * 160 + col] = make_float2(c[m2][t][0], c[m2][t][1]);
            *(float2*)&Cd[(size_t)(rowa + 8) * 160 + col] = make_float2(c[m2][t][2], c[m2][t][3]);
        }
    }
}

// ---------------------------------------------------------------------------
// k_pairE: layer-1 epilogue -> split-bf16 A', tensor layer-2, fused layer-3.
// ---------------------------------------------------------------------------
__global__ void __launch_bounds__(256) k_pairE(
    const float* __restrict__ pb1, const float* __restrict__ pb2,
    const float* __restrict__ pw3, const float* __restrict__ pb3,
    float* __restrict__ out)
{
    extern __shared__ __align__(16) char smE[];
    unsigned short* A2 = (unsigned short*)smE;
    char* W2b[2] = { smE + A2BYTES, smE + A2BYTES + W2CB };
    uint32_t W2u[2] = { smem_u32(W2b[0]), smem_u32(W2b[1]) };
    __shared__ int pis[32], pjs[32];
    __shared__ float rsum[64][2];

    int r0 = blockIdx.x * 32;
    int tid = threadIdx.x;
    int jg = tid >> 5;
    int hg = tid & 31;
    int h0 = 5 * hg;
    int lane = tid & 31, wid = tid >> 5;
    int g = lane >> 2, tg = lane & 3;
    int wm = wid & 3, wn = wid >> 2;

    if (tid < 32) { pis[tid] = d_pi[r0 + tid]; pjs[tid] = d_pj[r0 + tid]; }

    #pragma unroll
    for (int v = 0; v < 3; v++) {
        int unit = tid + 256 * v;
        if (unit < 640) {
            int n = unit >> 2, q = unit & 3;
            CP_ASYNC16(W2u[0] + n * 80 + q * 16,
                       (const char*)d_W2i + (size_t)n * 960 + q * 16);
        }
    }
    CP_COMMIT();

    {
        uint4 z = make_uint4(0, 0, 0, 0);
        uint4* a4 = (uint4*)A2;
        for (int idx = tid; idx < A2BYTES / 16; idx += 256) a4[idx] = z;
    }
    __syncthreads();

    #pragma unroll
    for (int jj = 0; jj < 4; jj++) {
        int t = 4 * jg + jj;
        int r = r0 + t;
        int pi = pis[t], pj = pjs[t];
        #pragma unroll
        for (int q = 0; q < 5; q++) {
            int h = h0 + q;
            if (h < HH) {
                size_t idx = (size_t)r * 160 + h;
                float cc = d_Cg2[0][idx] + d_Cg2[1][idx] + pb1[h];
                float vf = fmaxf(cc + d_A[pi * HH + h] + d_Bt[pj * HH + h], 0.f);
                float vt = fmaxf(cc + d_A[pj * HH + h] + d_Bt[pi * HH + h], 0.f);
                unsigned short hu, lu;
                split_bf16(vf, hu, lu);
                unsigned short* p = A2 + (size_t)t * 488 + 3 * h;
                p[0] = hu; p[1] = hu; p[2] = lu;
                split_bf16(vt, hu, lu);
                unsigned short* p2 = A2 + (size_t)(32 + t) * 488 + 3 * h;
                p2[0] = hu; p2[1] = hu; p2[2] = lu;
            }
        }
    }
    CP_WAIT0();
    __syncthreads();

    float c[10][4];
    #pragma unroll
    for (int t = 0; t < 10; t++)
        #pragma unroll
        for (int q = 0; q < 4; q++) c[t][q] = 0.f;

    for (int ch = 0; ch < 15; ch++) {
        int buf = ch & 1, nb = buf ^ 1;
        bool more = (ch + 1 < 15);
        if (more) {
            #pragma unroll
            for (int v = 0; v < 3; v++) {
                int unit = tid + 256 * v;
                if (unit < 640) {
                    int n = unit >> 2, q = unit & 3;
                    CP_ASYNC16(W2u[nb] + n * 80 + q * 16,
                               (const char*)d_W2i + (size_t)n * 960
                               + (ch + 1) * 64 + q * 16);
                }
            }
            CP_COMMIT();
        }
        const char* W = (const char*)W2b[buf];
        const char* A = (const char*)A2;
        #pragma unroll
        for (int s = 0; s < 2; s++) {
            int k0 = ch * 32 + s * 16;
            int ab = (16 * wm + g) * A2RS + (k0 + tg * 2) * 2;
            uint32_t a0 = *(const uint32_t*)(A + ab);
            uint32_t a1 = *(const uint32_t*)(A + ab + 8 * A2RS);
            uint32_t a2 = *(const uint32_t*)(A + ab + 16);
            uint32_t a3 = *(const uint32_t*)(A + ab + 8 * A2RS + 16);
            #pragma unroll
            for (int t = 0; t < 10; t++) {
                int wo = (wn * 80 + 8 * t + g) * 80 + s * 32 + tg * 4;
                uint32_t b0 = *(const uint32_t*)(W + wo);
                uint32_t b1 = *(const uint32_t*)(W + wo + 16);
                mma16816(c[t], a0, a1, a2, a3, b0, b1);
            }
        }
        if (more) { CP_WAIT0(); }
        __syncthreads();
    }

    float sg = 0.f, sg8 = 0.f;
    #pragma unroll
    for (int t = 0; t < 10; t++) {
        int n0 = wn * 80 + 8 * t + tg * 2;
        int n1 = n0 + 1;
        float b20 = (n0 < HH) ? pb2[n0] : 0.f;
        float b21 = (n1 < HH) ? pb2[n1] : 0.f;
        float w30 = (n0 < HH) ? pw3[n0] : 0.f;
        float w31 = (n1 < HH) ? pw3[n1] : 0.f;
        sg  += fmaxf(c[t][0] + b20, 0.f) * w30 + fmaxf(c[t][1] + b21, 0.f) * w31;
        sg8 += fmaxf(c[t][2] + b20, 0.f) * w30 + fmaxf(c[t][3] + b21, 0.f) * w31;
    }
    sg  += __shfl_xor_sync(0xffffffffu, sg, 1);
    sg  += __shfl_xor_sync(0xffffffffu, sg, 2);
    sg8 += __shfl_xor_sync(0xffffffffu, sg8, 1);
    sg8 += __shfl_xor_sync(0xffffffffu, sg8, 2);
    if (tg == 0) {
        rsum[16 * wm + g][wn] = sg;
        rsum[16 * wm + g + 8][wn] = sg8;
    }
    __syncthreads();

    if (tid < 64) {
        int row = tid;
        int t = row & 31;
        int fi, se;
        if (row < 32) { fi = pis[t]; se = pjs[t]; }
        else          { fi = pjs[t]; se = pis[t]; }
        float sc = rsum[row][0] + rsum[row][1] + pb3[0];
        float v = ((d_ms[fi] + d_ms[se]) + sc) * (1.f / 3.f);
        v = fminf(fmaxf(v, 0.f), 1.f);
        out[(size_t)fi * SS + (se % SS)] = v;
    }
}

// ---------------------------------------------------------------------------
extern "C" void kernel_launch(void* const* d_in, const int* in_sizes, int n_in,
                              void* d_out, int out_size)
{
    const float* X   = (const float*)d_in[0];
    const void*  sp  = d_in[1];
    const float* aw1 = (const float*)d_in[2];
    const float* ab1 = (const float*)d_in[3];
    const float* aw2 = (const float*)d_in[4];
    const float* ab2 = (const float*)d_in[5];
    const float* aw3 = (const float*)d_in[6];
    const float* ab3 = (const float*)d_in[7];
    const float* mw1 = (const float*)d_in[8];
    const float* mb1 = (const float*)d_in[9];
    const float* mw2 = (const float*)d_in[10];
    const float* mb2 = (const float*)d_in[11];
    const float* mw3 = (const float*)d_in[12];
    const float* mb3 = (const float*)d_in[13];
    const float* pw1 = (const float*)d_in[14];
    const float* pb1 = (const float*)d_in[15];
    const float* pw2 = (const float*)d_in[16];
    const float* pb2 = (const float*)d_in[17];
    const float* pw3 = (const float*)d_in[18];
    const float* pb3 = (const float*)d_in[19];
    float* out = (float*)d_out;

    cudaFuncSetAttribute(k_gemm, cudaFuncAttributeMaxDynamicSharedMemorySize,
                         SMEMG);
    cudaFuncSetAttribute(k_attn1g, cudaFuncAttributeMaxDynamicSharedMemorySize,
                         SMEMG);
    cudaFuncSetAttribute(k_pairE, cudaFuncAttributeMaxDynamicSharedMemorySize,
                         SMEMPE);

    const int wtot = 160 * (E3 + 768 + 160);
    k_prep0<<<73, 256>>>(sp);
    k_wprep<<<(wtot + 255) / 256, 256>>>(pw1, aw1, pw2);
    k_attn1g<<<96, 256, SMEMG>>>(X);
    k_attn2m<<<96, 256>>>(ab1, aw2, ab2, aw3, ab3);
    k_gather<<<NSPAN * 3, 256>>>(X);
    k_terms<<<288, 256>>>(pw1, mw1);
    k_redment<<<NSPAN, 160>>>(mb1, mw2, mb2, mw3, mb3);
    k_gemm<<<146, 256, SMEMG>>>();
    k_pairE<<<NPAIR / 32, 256, SMEMPE>>>(pb1, pb2, pw3, pb3, out);
}